// round 12
// baseline (speedup 1.0000x reference)
#include <cuda_runtime.h>
#include <cuda_bf16.h>
#include <cstdint>

// PositionwiseMaxPool2D: x [32,128,128,64] f32 NHWC, 2x2/2 pool.
// For each output pixel: pick window position with largest channel-vector
// squared L2 norm, copy its 64 floats to the output.
//
// FINAL (revert to R7, measured best 27.1us / kernel 23.8us, DRAM 75.8%):
// One warp per FOUR consecutive output pixels (same output row).
//   - 8 front-batched LDG.E.128 (.cs, touch-once input), fully coalesced
//     -> MLP_p1=8 with occ~50%: past the occ*MLP~5 saturation knee
//   - butterfly reduce within 16-lane halves + 1 cross-half shfl per norm
//   - branch-free argmax (first-index tie-break, matches jnp.argmax)
//   - evict-normal 256B stores: output lingers in L2, ~75% of the 33.5MB
//     writeback never reaches DRAM (measured: 142.5MB DRAM traffic vs
//     134.2MB compulsory reads)
// NO launch_bounds reg cap: the 8 resident float4s need the 48 regs; capping
// them serializes the load group and costs more than the occupancy it buys
// (measured R9: 40 regs -> DRAM 61.9%, 29.1us).

static constexpr int B  = 32;
static constexpr int H  = 128;
static constexpr int W  = 128;
static constexpr int C  = 64;
static constexpr int OH = 64;
static constexpr int OW = 64;
static constexpr int NOUT = B * OH * OW;   // 131072 output pixels
static constexpr int PIX_PER_WARP = 4;     // OW % 4 == 0 -> all 4 share input rows

__global__ __launch_bounds__(256)
void maxpool_pos_kernel(const float* __restrict__ x, float* __restrict__ out) {
    const int gw   = (blockIdx.x * blockDim.x + threadIdx.x) >> 5;  // warp id
    const int lane = threadIdx.x & 31;

    const int pix0 = gw << 2;                 // first of 4 output pixels
    const int ow0  = pix0 & (OW - 1);
    const int oh   = (pix0 >> 6) & (OH - 1);
    const int b    = pix0 >> 12;

    // input rows 2*oh, 2*oh+1 starting at column 2*ow0: 512 floats each
    const size_t base = ((size_t)((b * H + 2 * oh) * W + 2 * ow0)) * C;
    const float4* r0 = reinterpret_cast<const float4*>(x + base);
    const float4* r1 = r0 + (W * C) / 4;      // +32KB, next input row

    // 8 independent 512B loads -> 8 LDG.E.128 in flight before any use.
    // Chunk q of row r covers window q: floats [q*128, q*128+128)
    // = candidate (r, j=0) in lanes 0-15, (r, j=1) in lanes 16-31.
    // .cs: input is touch-once, evict-first in L1/L2.
    float4 v[8];
    #pragma unroll
    for (int q = 0; q < 4; q++) v[q]     = __ldcs(r0 + q * 32 + lane);
    #pragma unroll
    for (int q = 0; q < 4; q++) v[4 + q] = __ldcs(r1 + q * 32 + lane);

    // Per-lane squared-norm partials, butterfly-reduce within each 16-lane
    // half (xor offsets 1,2,4,8 never cross the half boundary).
    float s[8];
    #pragma unroll
    for (int q = 0; q < 8; q++) {
        s[q] = v[q].x * v[q].x + v[q].y * v[q].y
             + v[q].z * v[q].z + v[q].w * v[q].w;
    }
    #pragma unroll
    for (int off = 8; off; off >>= 1) {
        #pragma unroll
        for (int q = 0; q < 8; q++)
            s[q] += __shfl_xor_sync(0xffffffffu, s[q], off);
    }

    const bool hi = lane >= 16;
    float4* po = reinterpret_cast<float4*>(out + (size_t)pix0 * C);

    #pragma unroll
    for (int w = 0; w < 4; w++) {
        const float sA = s[w];        // (row 0, own column j)
        const float sB = s[4 + w];    // (row 1, own column j)
        const float oA = __shfl_xor_sync(0xffffffffu, sA, 16);
        const float oB = __shfl_xor_sync(0xffffffffu, sB, 16);

        const float n00 = hi ? oA : sA;
        const float n01 = hi ? sA : oA;
        const float n10 = hi ? oB : sB;
        const float n11 = hi ? sB : oB;

        // argmax, first-index tie-break (strict >) to match jnp.argmax
        int   k    = 0;
        float best = n00;
        if (n01 > best) { best = n01; k = 1; }
        if (n10 > best) { best = n10; k = 2; }
        if (n11 > best) { best = n11; k = 3; }

        // lanes of the winning column-half hold the winner's 64 floats.
        // Evict-normal store: let output linger in L2.
        if ((lane >> 4) == (k & 1)) {
            po[w * 16 + (lane & 15)] = (k >> 1) ? v[4 + w] : v[w];
        }
    }
}

extern "C" void kernel_launch(void* const* d_in, const int* in_sizes, int n_in,
                              void* d_out, int out_size) {
    const float* x = (const float*)d_in[0];
    float* out = (float*)d_out;
    // 131072/4 = 32768 warps; 8 warps/block -> 4096 blocks
    const int threads = 256;
    const int blocks  = (NOUT / PIX_PER_WARP) * 32 / threads;
    maxpool_pos_kernel<<<blocks, threads>>>(x, out);
}

// round 13
// speedup vs baseline: 1.1390x; 1.1390x over previous
#include <cuda_runtime.h>
#include <cuda_bf16.h>
#include <cstdint>

// PositionwiseMaxPool2D: x [32,128,128,64] f32 NHWC, 2x2/2 pool.
// For each output pixel: pick window position with largest channel-vector
// squared L2 norm, copy its 64 floats to the output.
//
// FINAL structure (R7 optimum; best measured 27.1us harness / 23.8us kernel,
// DRAM 75.8%, HBM 5993 GB/s). R12 re-ran this exact source and got 31.2us
// with every SM-side % inflated ~uniformly and HBM at 5112 GB/s: identical
// SASS, different clocks -> run-to-run DVFS/federation variance, not a
// kernel property. Re-benching unchanged per rigor.md.
//
// One warp per FOUR consecutive output pixels (same output row):
//   - 8 front-batched LDG.E.128 (.cs, touch-once input), fully coalesced
//     -> MLP_p1=8 at occ~50%: past the measured occ*MLP~5 saturation knee
//   - butterfly reduce within 16-lane halves + 1 cross-half shfl per norm
//   - branch-free argmax (first-index tie-break, matches jnp.argmax)
//   - evict-normal 256B stores: output lingers in L2; measured DRAM traffic
//     142.5MB vs 134.2MB compulsory reads (~75% of writeback absorbed)
// No launch_bounds reg cap: the 8 resident float4s ARE the 48 regs; capping
// serializes the load group (measured R9: 40 regs -> DRAM 61.9%, 29.1us).

static constexpr int B  = 32;
static constexpr int H  = 128;
static constexpr int W  = 128;
static constexpr int C  = 64;
static constexpr int OH = 64;
static constexpr int OW = 64;
static constexpr int NOUT = B * OH * OW;   // 131072 output pixels
static constexpr int PIX_PER_WARP = 4;     // OW % 4 == 0 -> all 4 share input rows

__global__ __launch_bounds__(256)
void maxpool_pos_kernel(const float* __restrict__ x, float* __restrict__ out) {
    const int gw   = (blockIdx.x * blockDim.x + threadIdx.x) >> 5;  // warp id
    const int lane = threadIdx.x & 31;

    const int pix0 = gw << 2;                 // first of 4 output pixels
    const int ow0  = pix0 & (OW - 1);
    const int oh   = (pix0 >> 6) & (OH - 1);
    const int b    = pix0 >> 12;

    // input rows 2*oh, 2*oh+1 starting at column 2*ow0: 512 floats each
    const size_t base = ((size_t)((b * H + 2 * oh) * W + 2 * ow0)) * C;
    const float4* r0 = reinterpret_cast<const float4*>(x + base);
    const float4* r1 = r0 + (W * C) / 4;      // +32KB, next input row

    // 8 independent 512B loads -> 8 LDG.E.128 in flight before any use.
    // Chunk q of row r covers window q: floats [q*128, q*128+128)
    // = candidate (r, j=0) in lanes 0-15, (r, j=1) in lanes 16-31.
    // .cs: input is touch-once, evict-first in L1/L2.
    float4 v[8];
    #pragma unroll
    for (int q = 0; q < 4; q++) v[q]     = __ldcs(r0 + q * 32 + lane);
    #pragma unroll
    for (int q = 0; q < 4; q++) v[4 + q] = __ldcs(r1 + q * 32 + lane);

    // Per-lane squared-norm partials, butterfly-reduce within each 16-lane
    // half (xor offsets 1,2,4,8 never cross the half boundary).
    float s[8];
    #pragma unroll
    for (int q = 0; q < 8; q++) {
        s[q] = v[q].x * v[q].x + v[q].y * v[q].y
             + v[q].z * v[q].z + v[q].w * v[q].w;
    }
    #pragma unroll
    for (int off = 8; off; off >>= 1) {
        #pragma unroll
        for (int q = 0; q < 8; q++)
            s[q] += __shfl_xor_sync(0xffffffffu, s[q], off);
    }

    const bool hi = lane >= 16;
    float4* po = reinterpret_cast<float4*>(out + (size_t)pix0 * C);

    #pragma unroll
    for (int w = 0; w < 4; w++) {
        const float sA = s[w];        // (row 0, own column j)
        const float sB = s[4 + w];    // (row 1, own column j)
        const float oA = __shfl_xor_sync(0xffffffffu, sA, 16);
        const float oB = __shfl_xor_sync(0xffffffffu, sB, 16);

        const float n00 = hi ? oA : sA;
        const float n01 = hi ? sA : oA;
        const float n10 = hi ? oB : sB;
        const float n11 = hi ? sB : oB;

        // argmax, first-index tie-break (strict >) to match jnp.argmax
        int   k    = 0;
        float best = n00;
        if (n01 > best) { best = n01; k = 1; }
        if (n10 > best) { best = n10; k = 2; }
        if (n11 > best) { best = n11; k = 3; }

        // lanes of the winning column-half hold the winner's 64 floats.
        // Evict-normal store: let output linger in L2.
        if ((lane >> 4) == (k & 1)) {
            po[w * 16 + (lane & 15)] = (k >> 1) ? v[4 + w] : v[w];
        }
    }
}

extern "C" void kernel_launch(void* const* d_in, const int* in_sizes, int n_in,
                              void* d_out, int out_size) {
    const float* x = (const float*)d_in[0];
    float* out = (float*)d_out;
    // 131072/4 = 32768 warps; 8 warps/block -> 4096 blocks
    const int threads = 256;
    const int blocks  = (NOUT / PIX_PER_WARP) * 32 / threads;
    maxpool_pos_kernel<<<blocks, threads>>>(x, out);
}